// round 1
// baseline (speedup 1.0000x reference)
#include <cuda_runtime.h>
#include <math.h>

#define BB   4
#define LL   4096
#define DD   1024
#define HH   16
#define DHH  64
#define MMF  256
#define DFF  4096
#define NT   (BB*LL)      /* 16384 tokens  */
#define NR   (NT*HH)      /* 262144 (t,h) rows */

// ---------------- scratch (device globals; no allocation allowed) ----------
__device__ float g_q   [(size_t)NT*DD];
__device__ float g_k   [(size_t)NT*DD];
__device__ float g_v   [(size_t)NT*DD];
__device__ float g_qp  [(size_t)NR*MMF];
__device__ float g_kp  [(size_t)NR*MMF];
__device__ float g_kv  [(size_t)BB*HH*MMF*DHH];
__device__ float g_ksum[BB*HH*MMF];
__device__ float g_den [NR];
__device__ float g_attn[(size_t)NT*DD];
__device__ float g_tmp [(size_t)NT*DD];
__device__ float g_out1[(size_t)NT*DD];
__device__ float g_hbuf[(size_t)NT*DFF];
__device__ float g_projT[DHH*MMF];
__device__ unsigned g_kmax;

enum { EPI_NONE = 0, EPI_BIAS = 1, EPI_BIAS_ELU = 2 };

// ---------------- big contiguous SGEMM: C[M,N] = A[M,K] @ B[K,N] ------------
template<int EPI>
__global__ __launch_bounds__(256)
void sgemm128(const float* __restrict__ A, const float* __restrict__ B,
              const float* __restrict__ bias, float* __restrict__ C,
              int M, int N, int K)
{
    __shared__ float As[16][128];
    __shared__ float Bs[16][128];
    const int tid = threadIdx.x;
    const int tx  = tid & 15;
    const int ty  = tid >> 4;
    const size_t m0 = (size_t)blockIdx.y * 128;
    const int    n0 = blockIdx.x * 128;

    float acc[8][8];
#pragma unroll
    for (int i = 0; i < 8; i++)
#pragma unroll
        for (int j = 0; j < 8; j++) acc[i][j] = 0.f;

    for (int k0 = 0; k0 < K; k0 += 16) {
#pragma unroll
        for (int i = 0; i < 2; i++) {            // A tile 128x16
            int lin = tid + i * 256;
            int ar  = lin >> 2;
            int ac  = (lin & 3) << 2;
            const float4 v = *(const float4*)(A + (m0 + ar) * K + k0 + ac);
            As[ac + 0][ar] = v.x; As[ac + 1][ar] = v.y;
            As[ac + 2][ar] = v.z; As[ac + 3][ar] = v.w;
        }
#pragma unroll
        for (int i = 0; i < 2; i++) {            // B tile 16x128
            int lin = tid + i * 256;
            int br  = lin >> 5;
            int bc  = (lin & 31) << 2;
            *(float4*)&Bs[br][bc] = *(const float4*)(B + (size_t)(k0 + br) * N + n0 + bc);
        }
        __syncthreads();
#pragma unroll
        for (int kk = 0; kk < 16; kk++) {
            float a[8], b[8];
#pragma unroll
            for (int i = 0; i < 8; i++) a[i] = As[kk][ty * 8 + i];
#pragma unroll
            for (int j = 0; j < 8; j++) b[j] = Bs[kk][tx * 8 + j];
#pragma unroll
            for (int i = 0; i < 8; i++)
#pragma unroll
                for (int j = 0; j < 8; j++) acc[i][j] += a[i] * b[j];
        }
        __syncthreads();
    }

#pragma unroll
    for (int i = 0; i < 8; i++) {
        size_t row = m0 + ty * 8 + i;
#pragma unroll
        for (int j = 0; j < 8; j += 4) {
            int col = n0 + tx * 8 + j;
            float4 o = make_float4(acc[i][j], acc[i][j+1], acc[i][j+2], acc[i][j+3]);
            if (EPI == EPI_BIAS || EPI == EPI_BIAS_ELU) {
                const float4 bb = *(const float4*)(bias + col);
                o.x += bb.x; o.y += bb.y; o.z += bb.z; o.w += bb.w;
            }
            if (EPI == EPI_BIAS_ELU) {
                o.x = o.x > 0.f ? o.x : expm1f(o.x);
                o.y = o.y > 0.f ? o.y : expm1f(o.y);
                o.z = o.z > 0.f ? o.z : expm1f(o.z);
                o.w = o.w > 0.f ? o.w : expm1f(o.w);
            }
            *(float4*)(C + row * N + col) = o;
        }
    }
}

// ------------- batched strided GEMM over (b,h): C = op(A) @ B ---------------
// z = b*16 + h. Tiles: BM=128, BN=64, BK=16, per-thread 8x4.
// TRANSA: A(row=m,k=l) element at Ab + k*lda + row   (row contiguous)
// else  : A(row,k)     element at Ab + row*lda + k   (k contiguous)
// DIV   : C /= aux[zb*sXb + zh*sXh + row*ldx]
template<bool TRANSA, bool DIV>
__global__ __launch_bounds__(256)
void sgemm_bh(const float* __restrict__ A, size_t sAb, size_t sAh, int lda,
              const float* __restrict__ B, size_t sBb, size_t sBh, int ldb,
              float* __restrict__ C, size_t sCb, size_t sCh, int ldc,
              const float* __restrict__ aux, size_t sXb, size_t sXh, int ldx,
              int M, int N, int K)
{
    __shared__ float As[16][128];
    __shared__ float Bs[16][64];
    const int z  = blockIdx.z;
    const int zb = z >> 4, zh = z & 15;
    const float* Ab = A + (size_t)zb * sAb + (size_t)zh * sAh;
    const float* Bb = B + (size_t)zb * sBb + (size_t)zh * sBh;
    float*       Cb = C + (size_t)zb * sCb + (size_t)zh * sCh;

    const int tid = threadIdx.x;
    const int tx  = tid & 15;
    const int ty  = tid >> 4;
    const int m0  = blockIdx.y * 128;
    const int n0  = blockIdx.x * 64;

    float acc[8][4];
#pragma unroll
    for (int i = 0; i < 8; i++)
#pragma unroll
        for (int j = 0; j < 4; j++) acc[i][j] = 0.f;

    for (int k0 = 0; k0 < K; k0 += 16) {
        if (TRANSA) {
#pragma unroll
            for (int i = 0; i < 2; i++) {
                int lin = tid + i * 256;
                int kc  = lin >> 5;
                int mc  = (lin & 31) << 2;
                *(float4*)&As[kc][mc] =
                    *(const float4*)(Ab + (size_t)(k0 + kc) * lda + m0 + mc);
            }
        } else {
#pragma unroll
            for (int i = 0; i < 2; i++) {
                int lin = tid + i * 256;
                int ar  = lin >> 2;
                int ac  = (lin & 3) << 2;
                const float4 v = *(const float4*)(Ab + (size_t)(m0 + ar) * lda + k0 + ac);
                As[ac + 0][ar] = v.x; As[ac + 1][ar] = v.y;
                As[ac + 2][ar] = v.z; As[ac + 3][ar] = v.w;
            }
        }
        {
            int kc = tid >> 4;
            int bc = (tid & 15) << 2;
            *(float4*)&Bs[kc][bc] =
                *(const float4*)(Bb + (size_t)(k0 + kc) * ldb + n0 + bc);
        }
        __syncthreads();
#pragma unroll
        for (int kk = 0; kk < 16; kk++) {
            float a[8], b[4];
#pragma unroll
            for (int i = 0; i < 8; i++) a[i] = As[kk][ty * 8 + i];
#pragma unroll
            for (int j = 0; j < 4; j++) b[j] = Bs[kk][tx * 4 + j];
#pragma unroll
            for (int i = 0; i < 8; i++)
#pragma unroll
                for (int j = 0; j < 4; j++) acc[i][j] += a[i] * b[j];
        }
        __syncthreads();
    }

#pragma unroll
    for (int i = 0; i < 8; i++) {
        int row = m0 + ty * 8 + i;
        float dv = 1.f;
        if (DIV)
            dv = 1.f / aux[(size_t)zb * sXb + (size_t)zh * sXh + (size_t)row * ldx];
        int col = n0 + tx * 4;
        float4 o = make_float4(acc[i][0] * dv, acc[i][1] * dv,
                               acc[i][2] * dv, acc[i][3] * dv);
        *(float4*)(Cb + (size_t)row * ldc + col) = o;
    }
}

// ---------------- small helper kernels --------------------------------------
__global__ void k_projT(const float* __restrict__ proj, float* __restrict__ pT)
{
    // proj[m][k] (256x64) -> pT[k][m] * dn, dn = 64^-0.25
    int i = blockIdx.x * 256 + threadIdx.x;     // 0..16383
    int m = i >> 6, k = i & 63;
    pT[k * 256 + m] = proj[i] * 0.35355339059327373f;
}

__global__ void k_max(const float4* __restrict__ d, size_t n4, unsigned* __restrict__ out)
{
    float m = -3.4e38f;
    for (size_t i = (size_t)blockIdx.x * blockDim.x + threadIdx.x; i < n4;
         i += (size_t)gridDim.x * blockDim.x) {
        float4 v = d[i];
        m = fmaxf(m, fmaxf(fmaxf(v.x, v.y), fmaxf(v.z, v.w)));
    }
#pragma unroll
    for (int o = 16; o; o >>= 1) m = fmaxf(m, __shfl_xor_sync(0xffffffffu, m, o));
    __shared__ float sm[8];
    if ((threadIdx.x & 31) == 0) sm[threadIdx.x >> 5] = m;
    __syncthreads();
    if (threadIdx.x == 0) {
        float mm = sm[0];
        for (int i = 1; i < 8; i++) mm = fmaxf(mm, sm[i]);
        unsigned u = __float_as_uint(mm);
        u = (u & 0x80000000u) ? ~u : (u | 0x80000000u);
        atomicMax(out, u);
    }
}

__device__ __forceinline__ float unflip(unsigned u)
{
    return __uint_as_float((u & 0x80000000u) ? (u ^ 0x80000000u) : ~u);
}

// qp = ratio*(exp(dd - diag - rowmax) + eps), in place; warp per (t,h) row.
__global__ void k_expq(float* __restrict__ dd, const float* __restrict__ q)
{
    size_t w   = ((size_t)blockIdx.x * blockDim.x + threadIdx.x) >> 5;
    int   lane = threadIdx.x & 31;
    float4* row = (float4*)(dd + w * 256);
    float4 v0 = row[lane];
    float4 v1 = row[lane + 32];
    float m = fmaxf(fmaxf(fmaxf(v0.x, v0.y), fmaxf(v0.z, v0.w)),
                    fmaxf(fmaxf(v1.x, v1.y), fmaxf(v1.z, v1.w)));
#pragma unroll
    for (int o = 16; o; o >>= 1) m = fmaxf(m, __shfl_xor_sync(0xffffffffu, m, o));
    float2 qq = ((const float2*)(q + w * 64))[lane];
    float ss = qq.x * qq.x + qq.y * qq.y;
#pragma unroll
    for (int o = 16; o; o >>= 1) ss += __shfl_xor_sync(0xffffffffu, ss, o);
    float c = 0.0625f * ss + m;                 // 0.5*dn^2 = 1/16
    v0.x = 0.0625f * (expf(v0.x - c) + 1e-6f);
    v0.y = 0.0625f * (expf(v0.y - c) + 1e-6f);
    v0.z = 0.0625f * (expf(v0.z - c) + 1e-6f);
    v0.w = 0.0625f * (expf(v0.w - c) + 1e-6f);
    v1.x = 0.0625f * (expf(v1.x - c) + 1e-6f);
    v1.y = 0.0625f * (expf(v1.y - c) + 1e-6f);
    v1.z = 0.0625f * (expf(v1.z - c) + 1e-6f);
    v1.w = 0.0625f * (expf(v1.w - c) + 1e-6f);
    row[lane] = v0; row[lane + 32] = v1;
}

// kp = ratio*(exp(dd - diag - globalmax) + eps), in place.
__global__ void k_expk(float* __restrict__ dd, const float* __restrict__ k,
                       const unsigned* __restrict__ gmax)
{
    size_t w   = ((size_t)blockIdx.x * blockDim.x + threadIdx.x) >> 5;
    int   lane = threadIdx.x & 31;
    float4* row = (float4*)(dd + w * 256);
    float4 v0 = row[lane];
    float4 v1 = row[lane + 32];
    float2 kk = ((const float2*)(k + w * 64))[lane];
    float ss = kk.x * kk.x + kk.y * kk.y;
#pragma unroll
    for (int o = 16; o; o >>= 1) ss += __shfl_xor_sync(0xffffffffu, ss, o);
    float c = 0.0625f * ss + unflip(*gmax);
    v0.x = 0.0625f * (expf(v0.x - c) + 1e-6f);
    v0.y = 0.0625f * (expf(v0.y - c) + 1e-6f);
    v0.z = 0.0625f * (expf(v0.z - c) + 1e-6f);
    v0.w = 0.0625f * (expf(v0.w - c) + 1e-6f);
    v1.x = 0.0625f * (expf(v1.x - c) + 1e-6f);
    v1.y = 0.0625f * (expf(v1.y - c) + 1e-6f);
    v1.z = 0.0625f * (expf(v1.z - c) + 1e-6f);
    v1.w = 0.0625f * (expf(v1.w - c) + 1e-6f);
    row[lane] = v0; row[lane + 32] = v1;
}

// ksum[b,h,m] = sum_l kp[b,l,h,m]; grid (8 chunks, 64 bh), 256 threads (m)
__global__ void k_ksum(const float* __restrict__ kp, float* __restrict__ ksum)
{
    int z = blockIdx.y;
    int b = z >> 4, h = z & 15;
    int m = threadIdx.x;
    size_t base = (size_t)b * 16777216 + (size_t)h * 256 + m;
    float s = 0.f;
    int l0 = blockIdx.x * 512;
    for (int l = l0; l < l0 + 512; l++) s += kp[base + (size_t)l * 4096];
    atomicAdd(&ksum[z * 256 + m], s);
}

// denom[r] = dot(qp[r,:], ksum[b,h,:]); warp per row
__global__ void k_denom(const float* __restrict__ qp, const float* __restrict__ ksum,
                        float* __restrict__ den)
{
    size_t w   = ((size_t)blockIdx.x * blockDim.x + threadIdx.x) >> 5;
    int   lane = threadIdx.x & 31;
    int   b    = (int)(w >> 16);
    int   h    = (int)(w & 15);
    const float4* row = (const float4*)(qp + w * 256);
    const float4* ks  = (const float4*)(ksum + ((size_t)b * 16 + h) * 256);
    float4 a0 = row[lane], a1 = row[lane + 32];
    float4 k0 = ks[lane],  k1 = ks[lane + 32];
    float s = a0.x * k0.x + a0.y * k0.y + a0.z * k0.z + a0.w * k0.w
            + a1.x * k1.x + a1.y * k1.y + a1.z * k1.z + a1.w * k1.w;
#pragma unroll
    for (int o = 16; o; o >>= 1) s += __shfl_xor_sync(0xffffffffu, s, o);
    if (lane == 0) den[w] = s;
}

// out = LN(a + r) * g + b ; one block per 1024-wide row
__global__ void k_ln(const float* __restrict__ a, const float* __restrict__ r,
                     const float* __restrict__ g, const float* __restrict__ b,
                     float* __restrict__ out)
{
    const int row = blockIdx.x;
    const int t   = threadIdx.x;
    const size_t base = (size_t)row * 1024;
    float4 xa = *(const float4*)(a + base + t * 4);
    float4 xr = *(const float4*)(r + base + t * 4);
    float4 s  = make_float4(xa.x + xr.x, xa.y + xr.y, xa.z + xr.z, xa.w + xr.w);
    float sum = s.x + s.y + s.z + s.w;
    float sq  = s.x * s.x + s.y * s.y + s.z * s.z + s.w * s.w;
#pragma unroll
    for (int o = 16; o; o >>= 1) {
        sum += __shfl_xor_sync(0xffffffffu, sum, o);
        sq  += __shfl_xor_sync(0xffffffffu, sq,  o);
    }
    __shared__ float ssum[8], ssq[8];
    __shared__ float s_mu, s_inv;
    int w = t >> 5;
    if ((t & 31) == 0) { ssum[w] = sum; ssq[w] = sq; }
    __syncthreads();
    if (t == 0) {
        float ts = 0.f, tq = 0.f;
        for (int i = 0; i < 8; i++) { ts += ssum[i]; tq += ssq[i]; }
        float mu  = ts * (1.f / 1024.f);
        float var = tq * (1.f / 1024.f) - mu * mu;
        s_mu = mu;
        s_inv = rsqrtf(var + 1e-6f);
    }
    __syncthreads();
    float mu = s_mu, inv = s_inv;
    float4 gg = *(const float4*)(g + t * 4);
    float4 bb = *(const float4*)(b + t * 4);
    float4 o = make_float4((s.x - mu) * inv * gg.x + bb.x,
                           (s.y - mu) * inv * gg.y + bb.y,
                           (s.z - mu) * inv * gg.z + bb.z,
                           (s.w - mu) * inv * gg.w + bb.w);
    *(float4*)(out + base + t * 4) = o;
}

// ---------------- driver -----------------------------------------------------
extern "C" void kernel_launch(void* const* d_in, const int* in_sizes, int n_in,
                              void* d_out, int out_size)
{
    const float* x    = (const float*)d_in[0];
    const float* wq   = (const float*)d_in[1];
    const float* wk   = (const float*)d_in[2];
    const float* wv   = (const float*)d_in[3];
    const float* wo   = (const float*)d_in[4];
    const float* proj = (const float*)d_in[5];
    const float* ln1g = (const float*)d_in[6];
    const float* ln1b = (const float*)d_in[7];
    const float* ln2g = (const float*)d_in[8];
    const float* ln2b = (const float*)d_in[9];
    const float* w1   = (const float*)d_in[10];
    const float* b1   = (const float*)d_in[11];
    const float* w2   = (const float*)d_in[12];
    const float* b2   = (const float*)d_in[13];
    float* out = (float*)d_out;

    float *p_q, *p_k, *p_v, *p_qp, *p_kp, *p_kv, *p_ksum, *p_den;
    float *p_attn, *p_tmp, *p_out1, *p_h, *p_pT;
    unsigned* p_kmax;
    cudaGetSymbolAddress((void**)&p_q,    g_q);
    cudaGetSymbolAddress((void**)&p_k,    g_k);
    cudaGetSymbolAddress((void**)&p_v,    g_v);
    cudaGetSymbolAddress((void**)&p_qp,   g_qp);
    cudaGetSymbolAddress((void**)&p_kp,   g_kp);
    cudaGetSymbolAddress((void**)&p_kv,   g_kv);
    cudaGetSymbolAddress((void**)&p_ksum, g_ksum);
    cudaGetSymbolAddress((void**)&p_den,  g_den);
    cudaGetSymbolAddress((void**)&p_attn, g_attn);
    cudaGetSymbolAddress((void**)&p_tmp,  g_tmp);
    cudaGetSymbolAddress((void**)&p_out1, g_out1);
    cudaGetSymbolAddress((void**)&p_h,    g_hbuf);
    cudaGetSymbolAddress((void**)&p_pT,   g_projT);
    cudaGetSymbolAddress((void**)&p_kmax, g_kmax);

    // projT = dn * proj^T
    k_projT<<<64, 256>>>(proj, p_pT);

    // q,k,v projections: [16384,1024] = x @ w  (w flattens to [1024,1024])
    sgemm128<EPI_NONE><<<dim3(8, 128), 256>>>(x, wq, nullptr, p_q, NT, 1024, 1024);
    sgemm128<EPI_NONE><<<dim3(8, 128), 256>>>(x, wk, nullptr, p_k, NT, 1024, 1024);
    sgemm128<EPI_NONE><<<dim3(8, 128), 256>>>(x, wv, nullptr, p_v, NT, 1024, 1024);

    // dd = q_resh[262144,64] @ projT[64,256]  (same for k)
    sgemm128<EPI_NONE><<<dim3(2, 2048), 256>>>(p_q, p_pT, nullptr, p_qp, NR, 256, 64);
    sgemm128<EPI_NONE><<<dim3(2, 2048), 256>>>(p_k, p_pT, nullptr, p_kp, NR, 256, 64);

    cudaMemsetAsync(p_kmax, 0, 4);
    cudaMemsetAsync(p_ksum, 0, BB * HH * MMF * sizeof(float));

    // global max over key dd
    k_max<<<2048, 256>>>((const float4*)p_kp, (size_t)NR * 64, p_kmax);

    // feature maps in place
    k_expq<<<NR / 8, 256>>>(p_qp, p_q);
    k_expk<<<NR / 8, 256>>>(p_kp, p_k, p_kmax);

    // kv[bh][256][64] = kp^T @ v per (b,h):  M=256 N=64 K=4096
    sgemm_bh<true, false><<<dim3(1, 2, 64), 256>>>(
        p_kp, (size_t)16777216, (size_t)256, 4096,
        p_v,  (size_t)4194304,  (size_t)64,  1024,
        p_kv, (size_t)(16 * 16384), (size_t)16384, 64,
        nullptr, 0, 0, 0,
        256, 64, 4096);

    // ksum
    k_ksum<<<dim3(8, 64), 256>>>(p_kp, p_ksum);

    // denom per (t,h)
    k_denom<<<NR / 8, 256>>>(p_qp, p_ksum, p_den);

    // attn = (qp @ kv) / denom per (b,h): M=4096 N=64 K=256
    sgemm_bh<false, true><<<dim3(1, 32, 64), 256>>>(
        p_qp, (size_t)16777216, (size_t)256, 4096,
        p_kv, (size_t)(16 * 16384), (size_t)16384, 64,
        p_attn, (size_t)4194304, (size_t)64, 1024,
        p_den,  (size_t)65536,   (size_t)1,  16,
        4096, 64, 256);

    // attn_out = attn @ wo  (wo flattens to [1024,1024], rows = h*64+k)
    sgemm128<EPI_NONE><<<dim3(8, 128), 256>>>(p_attn, wo, nullptr, p_tmp, NT, 1024, 1024);

    // out1 = LN(x + attn_out)
    k_ln<<<NT, 256>>>(p_tmp, x, ln1g, ln1b, p_out1);

    // FFN
    sgemm128<EPI_BIAS_ELU><<<dim3(32, 128), 256>>>(p_out1, w1, b1, p_h, NT, DFF, 1024);
    sgemm128<EPI_BIAS><<<dim3(8, 128), 256>>>(p_h, w2, b2, p_tmp, NT, 1024, DFF);

    // out2 = LN(out1 + ffn)
    k_ln<<<NT, 256>>>(p_tmp, p_out1, ln2g, ln2b, out);
}

// round 2
// speedup vs baseline: 2.4751x; 2.4751x over previous
#include <cuda_runtime.h>
#include <math.h>

#define BB   4
#define LL   4096
#define DD   1024
#define HH   16
#define DHH  64
#define MMF  256
#define DFF  4096
#define NT   (BB*LL)      /* 16384 tokens  */
#define NR   (NT*HH)      /* 262144 (t,h) rows */

// ---------------- scratch (device globals; no allocation allowed) ----------
__device__ float g_q   [(size_t)NT*DD];
__device__ float g_k   [(size_t)NT*DD];
__device__ float g_v   [(size_t)NT*DD];
__device__ float g_qp  [(size_t)NR*MMF];
__device__ float g_kp  [(size_t)NR*MMF];
__device__ float g_kv  [(size_t)BB*HH*MMF*DHH];
__device__ float g_ksum[BB*HH*MMF];
__device__ float g_den [NR];
__device__ float g_attn[(size_t)NT*DD];
__device__ float g_tmp [(size_t)NT*DD];
__device__ float g_out1[(size_t)NT*DD];
__device__ float g_hbuf[(size_t)NT*DFF];
__device__ float g_projT[DHH*MMF];
__device__ unsigned g_kmax;

enum { EPI_NONE = 0, EPI_BIAS = 1, EPI_BIAS_ELU = 2 };

// ---------------- tf32 helpers ----------------------------------------------
__device__ __forceinline__ unsigned f2tf32(float x)
{
    unsigned y;
    asm("cvt.rna.tf32.f32 %0, %1;" : "=r"(y) : "f"(x));
    return y;
}

__device__ __forceinline__ void mma_tf32(float* d, const unsigned* a,
                                         const unsigned* b)
{
    asm volatile(
        "mma.sync.aligned.m16n8k8.row.col.f32.tf32.tf32.f32 "
        "{%0,%1,%2,%3}, {%4,%5,%6,%7}, {%8,%9}, {%0,%1,%2,%3};\n"
        : "+f"(d[0]), "+f"(d[1]), "+f"(d[2]), "+f"(d[3])
        : "r"(a[0]), "r"(a[1]), "r"(a[2]), "r"(a[3]),
          "r"(b[0]), "r"(b[1]));
}

// ---------------- tf32 tensor-core GEMM: C[M,N] = A[M,K] @ B[K,N] ------------
// 128x128 block tile, BK=16, 256 threads = 8 warps (4 along M x 2 along N),
// warp tile 32x64 via m16n8k8 (2 m-tiles x 8 n-tiles).
#define APAD 20    /* As row stride (words): 128 rows x 20 */
#define BPAD 136   /* Bs row stride (words): 16 rows x 136 */

template<int EPI>
__global__ __launch_bounds__(256, 2)
void tgemm(const float* __restrict__ A, const float* __restrict__ B,
           const float* __restrict__ bias, float* __restrict__ C,
           int M, int N, int K)
{
    __shared__ unsigned As[128 * APAD];
    __shared__ unsigned Bs[16 * BPAD];

    const int tid  = threadIdx.x;
    const int wid  = tid >> 5;
    const int lane = tid & 31;
    const int wm   = (wid >> 1) * 32;   // warp m offset within tile
    const int wn   = (wid & 1)  * 64;   // warp n offset within tile
    const size_t m0 = (size_t)blockIdx.y * 128;
    const int    n0 = blockIdx.x * 128;

    // gmem->reg staging indices
    const int arow = tid >> 2;          // 0..63 -> two rows via +64
    const int acol = (tid & 3) << 2;
    const int brow = tid >> 5;          // 0..7  -> two rows via +8
    const int bcol = (tid & 31) << 2;

    float4 ra[2], rb[2];
    float acc[2][8][4];
#pragma unroll
    for (int mt = 0; mt < 2; mt++)
#pragma unroll
        for (int nt = 0; nt < 8; nt++)
#pragma unroll
            for (int i = 0; i < 4; i++) acc[mt][nt][i] = 0.f;

    const int iters = K >> 4;

    // prologue load
    ra[0] = *(const float4*)(A + (m0 + arow)      * K + acol);
    ra[1] = *(const float4*)(A + (m0 + arow + 64) * K + acol);
    rb[0] = *(const float4*)(B + (size_t)(brow)     * N + n0 + bcol);
    rb[1] = *(const float4*)(B + (size_t)(brow + 8) * N + n0 + bcol);

    for (int it = 0; it < iters; it++) {
        // store staged tile (convert to tf32 bits)
#pragma unroll
        for (int i = 0; i < 2; i++) {
            unsigned* p = &As[(arow + i * 64) * APAD + acol];
            p[0] = f2tf32(ra[i].x); p[1] = f2tf32(ra[i].y);
            p[2] = f2tf32(ra[i].z); p[3] = f2tf32(ra[i].w);
        }
#pragma unroll
        for (int i = 0; i < 2; i++) {
            unsigned* p = &Bs[(brow + i * 8) * BPAD + bcol];
            p[0] = f2tf32(rb[i].x); p[1] = f2tf32(rb[i].y);
            p[2] = f2tf32(rb[i].z); p[3] = f2tf32(rb[i].w);
        }
        __syncthreads();

        // prefetch next tile
        if (it + 1 < iters) {
            int k0 = (it + 1) << 4;
            ra[0] = *(const float4*)(A + (m0 + arow)      * K + k0 + acol);
            ra[1] = *(const float4*)(A + (m0 + arow + 64) * K + k0 + acol);
            rb[0] = *(const float4*)(B + (size_t)(k0 + brow)     * N + n0 + bcol);
            rb[1] = *(const float4*)(B + (size_t)(k0 + brow + 8) * N + n0 + bcol);
        }

        // compute: 2 k-steps of 8
#pragma unroll
        for (int ks = 0; ks < 16; ks += 8) {
            unsigned af[2][4], bf[8][2];
#pragma unroll
            for (int mt = 0; mt < 2; mt++) {
                int r = wm + mt * 16 + (lane >> 2);
                int c = ks + (lane & 3);
                af[mt][0] = As[r * APAD + c];
                af[mt][1] = As[(r + 8) * APAD + c];
                af[mt][2] = As[r * APAD + c + 4];
                af[mt][3] = As[(r + 8) * APAD + c + 4];
            }
#pragma unroll
            for (int nt = 0; nt < 8; nt++) {
                int c = wn + nt * 8 + (lane >> 2);
                int r = ks + (lane & 3);
                bf[nt][0] = Bs[r * BPAD + c];
                bf[nt][1] = Bs[(r + 4) * BPAD + c];
            }
#pragma unroll
            for (int mt = 0; mt < 2; mt++)
#pragma unroll
                for (int nt = 0; nt < 8; nt++)
                    mma_tf32(acc[mt][nt], af[mt], bf[nt]);
        }
        __syncthreads();
    }

    // epilogue: c0,c1 at (row, 2q..2q+1); c2,c3 at (row+8, same)
#pragma unroll
    for (int mt = 0; mt < 2; mt++) {
#pragma unroll
        for (int nt = 0; nt < 8; nt++) {
            size_t row = m0 + wm + mt * 16 + (lane >> 2);
            int col = n0 + wn + nt * 8 + ((lane & 3) << 1);
            float2 lo = make_float2(acc[mt][nt][0], acc[mt][nt][1]);
            float2 hi = make_float2(acc[mt][nt][2], acc[mt][nt][3]);
            if (EPI == EPI_BIAS || EPI == EPI_BIAS_ELU) {
                float2 bb = *(const float2*)(bias + col);
                lo.x += bb.x; lo.y += bb.y;
                hi.x += bb.x; hi.y += bb.y;
            }
            if (EPI == EPI_BIAS_ELU) {
                lo.x = lo.x > 0.f ? lo.x : expm1f(lo.x);
                lo.y = lo.y > 0.f ? lo.y : expm1f(lo.y);
                hi.x = hi.x > 0.f ? hi.x : expm1f(hi.x);
                hi.y = hi.y > 0.f ? hi.y : expm1f(hi.y);
            }
            *(float2*)(C + row * N + col)       = lo;
            *(float2*)(C + (row + 8) * N + col) = hi;
        }
    }
}

// ------------- batched strided GEMM over (b,h): C = op(A) @ B (fp32) --------
template<bool TRANSA, bool DIV>
__global__ __launch_bounds__(256)
void sgemm_bh(const float* __restrict__ A, size_t sAb, size_t sAh, int lda,
              const float* __restrict__ B, size_t sBb, size_t sBh, int ldb,
              float* __restrict__ C, size_t sCb, size_t sCh, int ldc,
              const float* __restrict__ aux, size_t sXb, size_t sXh, int ldx,
              int M, int N, int K)
{
    __shared__ float As[16][128];
    __shared__ float Bs[16][64];
    const int z  = blockIdx.z;
    const int zb = z >> 4, zh = z & 15;
    const float* Ab = A + (size_t)zb * sAb + (size_t)zh * sAh;
    const float* Bb = B + (size_t)zb * sBb + (size_t)zh * sBh;
    float*       Cb = C + (size_t)zb * sCb + (size_t)zh * sCh;

    const int tid = threadIdx.x;
    const int tx  = tid & 15;
    const int ty  = tid >> 4;
    const int m0  = blockIdx.y * 128;
    const int n0  = blockIdx.x * 64;

    float acc[8][4];
#pragma unroll
    for (int i = 0; i < 8; i++)
#pragma unroll
        for (int j = 0; j < 4; j++) acc[i][j] = 0.f;

    for (int k0 = 0; k0 < K; k0 += 16) {
        if (TRANSA) {
#pragma unroll
            for (int i = 0; i < 2; i++) {
                int lin = tid + i * 256;
                int kc  = lin >> 5;
                int mc  = (lin & 31) << 2;
                *(float4*)&As[kc][mc] =
                    *(const float4*)(Ab + (size_t)(k0 + kc) * lda + m0 + mc);
            }
        } else {
#pragma unroll
            for (int i = 0; i < 2; i++) {
                int lin = tid + i * 256;
                int ar  = lin >> 2;
                int ac  = (lin & 3) << 2;
                const float4 v = *(const float4*)(Ab + (size_t)(m0 + ar) * lda + k0 + ac);
                As[ac + 0][ar] = v.x; As[ac + 1][ar] = v.y;
                As[ac + 2][ar] = v.z; As[ac + 3][ar] = v.w;
            }
        }
        {
            int kc = tid >> 4;
            int bc = (tid & 15) << 2;
            *(float4*)&Bs[kc][bc] =
                *(const float4*)(Bb + (size_t)(k0 + kc) * ldb + n0 + bc);
        }
        __syncthreads();
#pragma unroll
        for (int kk = 0; kk < 16; kk++) {
            float a[8], b[4];
#pragma unroll
            for (int i = 0; i < 8; i++) a[i] = As[kk][ty * 8 + i];
#pragma unroll
            for (int j = 0; j < 4; j++) b[j] = Bs[kk][tx * 4 + j];
#pragma unroll
            for (int i = 0; i < 8; i++)
#pragma unroll
                for (int j = 0; j < 4; j++) acc[i][j] += a[i] * b[j];
        }
        __syncthreads();
    }

#pragma unroll
    for (int i = 0; i < 8; i++) {
        int row = m0 + ty * 8 + i;
        float dv = 1.f;
        if (DIV)
            dv = 1.f / aux[(size_t)zb * sXb + (size_t)zh * sXh + (size_t)row * ldx];
        int col = n0 + tx * 4;
        float4 o = make_float4(acc[i][0] * dv, acc[i][1] * dv,
                               acc[i][2] * dv, acc[i][3] * dv);
        *(float4*)(Cb + (size_t)row * ldc + col) = o;
    }
}

// ---------------- small helper kernels --------------------------------------
__global__ void k_projT(const float* __restrict__ proj, float* __restrict__ pT)
{
    // proj[m][k] (256x64) -> pT[k][m] * dn, dn = 64^-0.25
    int i = blockIdx.x * 256 + threadIdx.x;     // 0..16383
    int m = i >> 6, k = i & 63;
    pT[k * 256 + m] = proj[i] * 0.35355339059327373f;
}

__global__ void k_max(const float4* __restrict__ d, size_t n4, unsigned* __restrict__ out)
{
    float m = -3.4e38f;
    for (size_t i = (size_t)blockIdx.x * blockDim.x + threadIdx.x; i < n4;
         i += (size_t)gridDim.x * blockDim.x) {
        float4 v = d[i];
        m = fmaxf(m, fmaxf(fmaxf(v.x, v.y), fmaxf(v.z, v.w)));
    }
#pragma unroll
    for (int o = 16; o; o >>= 1) m = fmaxf(m, __shfl_xor_sync(0xffffffffu, m, o));
    __shared__ float sm[8];
    if ((threadIdx.x & 31) == 0) sm[threadIdx.x >> 5] = m;
    __syncthreads();
    if (threadIdx.x == 0) {
        float mm = sm[0];
        for (int i = 1; i < 8; i++) mm = fmaxf(mm, sm[i]);
        unsigned u = __float_as_uint(mm);
        u = (u & 0x80000000u) ? ~u : (u | 0x80000000u);
        atomicMax(out, u);
    }
}

__device__ __forceinline__ float unflip(unsigned u)
{
    return __uint_as_float((u & 0x80000000u) ? (u ^ 0x80000000u) : ~u);
}

// qp = ratio*(exp(dd - diag - rowmax) + eps), in place; warp per (t,h) row.
__global__ void k_expq(float* __restrict__ dd, const float* __restrict__ q)
{
    size_t w   = ((size_t)blockIdx.x * blockDim.x + threadIdx.x) >> 5;
    int   lane = threadIdx.x & 31;
    float4* row = (float4*)(dd + w * 256);
    float4 v0 = row[lane];
    float4 v1 = row[lane + 32];
    float m = fmaxf(fmaxf(fmaxf(v0.x, v0.y), fmaxf(v0.z, v0.w)),
                    fmaxf(fmaxf(v1.x, v1.y), fmaxf(v1.z, v1.w)));
#pragma unroll
    for (int o = 16; o; o >>= 1) m = fmaxf(m, __shfl_xor_sync(0xffffffffu, m, o));
    float2 qq = ((const float2*)(q + w * 64))[lane];
    float ss = qq.x * qq.x + qq.y * qq.y;
#pragma unroll
    for (int o = 16; o; o >>= 1) ss += __shfl_xor_sync(0xffffffffu, ss, o);
    float c = 0.0625f * ss + m;                 // 0.5*dn^2 = 1/16
    v0.x = 0.0625f * (expf(v0.x - c) + 1e-6f);
    v0.y = 0.0625f * (expf(v0.y - c) + 1e-6f);
    v0.z = 0.0625f * (expf(v0.z - c) + 1e-6f);
    v0.w = 0.0625f * (expf(v0.w - c) + 1e-6f);
    v1.x = 0.0625f * (expf(v1.x - c) + 1e-6f);
    v1.y = 0.0625f * (expf(v1.y - c) + 1e-6f);
    v1.z = 0.0625f * (expf(v1.z - c) + 1e-6f);
    v1.w = 0.0625f * (expf(v1.w - c) + 1e-6f);
    row[lane] = v0; row[lane + 32] = v1;
}

// kp = ratio*(exp(dd - diag - globalmax) + eps), in place.
__global__ void k_expk(float* __restrict__ dd, const float* __restrict__ k,
                       const unsigned* __restrict__ gmax)
{
    size_t w   = ((size_t)blockIdx.x * blockDim.x + threadIdx.x) >> 5;
    int   lane = threadIdx.x & 31;
    float4* row = (float4*)(dd + w * 256);
    float4 v0 = row[lane];
    float4 v1 = row[lane + 32];
    float2 kk = ((const float2*)(k + w * 64))[lane];
    float ss = kk.x * kk.x + kk.y * kk.y;
#pragma unroll
    for (int o = 16; o; o >>= 1) ss += __shfl_xor_sync(0xffffffffu, ss, o);
    float c = 0.0625f * ss + unflip(*gmax);
    v0.x = 0.0625f * (expf(v0.x - c) + 1e-6f);
    v0.y = 0.0625f * (expf(v0.y - c) + 1e-6f);
    v0.z = 0.0625f * (expf(v0.z - c) + 1e-6f);
    v0.w = 0.0625f * (expf(v0.w - c) + 1e-6f);
    v1.x = 0.0625f * (expf(v1.x - c) + 1e-6f);
    v1.y = 0.0625f * (expf(v1.y - c) + 1e-6f);
    v1.z = 0.0625f * (expf(v1.z - c) + 1e-6f);
    v1.w = 0.0625f * (expf(v1.w - c) + 1e-6f);
    row[lane] = v0; row[lane + 32] = v1;
}

// ksum[b,h,m] = sum_l kp[b,l,h,m]; grid (8 chunks, 64 bh), 256 threads (m)
__global__ void k_ksum(const float* __restrict__ kp, float* __restrict__ ksum)
{
    int z = blockIdx.y;
    int b = z >> 4, h = z & 15;
    int m = threadIdx.x;
    size_t base = (size_t)b * 16777216 + (size_t)h * 256 + m;
    float s = 0.f;
    int l0 = blockIdx.x * 512;
    for (int l = l0; l < l0 + 512; l++) s += kp[base + (size_t)l * 4096];
    atomicAdd(&ksum[z * 256 + m], s);
}

// denom[r] = dot(qp[r,:], ksum[b,h,:]); warp per row
__global__ void k_denom(const float* __restrict__ qp, const float* __restrict__ ksum,
                        float* __restrict__ den)
{
    size_t w   = ((size_t)blockIdx.x * blockDim.x + threadIdx.x) >> 5;
    int   lane = threadIdx.x & 31;
    int   b    = (int)(w >> 16);
    int   h    = (int)(w & 15);
    const float4* row = (const float4*)(qp + w * 256);
    const float4* ks  = (const float4*)(ksum + ((size_t)b * 16 + h) * 256);
    float4 a0 = row[lane], a1 = row[lane + 32];
    float4 k0 = ks[lane],  k1 = ks[lane + 32];
    float s = a0.x * k0.x + a0.y * k0.y + a0.z * k0.z + a0.w * k0.w
            + a1.x * k1.x + a1.y * k1.y + a1.z * k1.z + a1.w * k1.w;
#pragma unroll
    for (int o = 16; o; o >>= 1) s += __shfl_xor_sync(0xffffffffu, s, o);
    if (lane == 0) den[w] = s;
}

// out = LN(a + r) * g + b ; one block per 1024-wide row
__global__ void k_ln(const float* __restrict__ a, const float* __restrict__ r,
                     const float* __restrict__ g, const float* __restrict__ b,
                     float* __restrict__ out)
{
    const int row = blockIdx.x;
    const int t   = threadIdx.x;
    const size_t base = (size_t)row * 1024;
    float4 xa = *(const float4*)(a + base + t * 4);
    float4 xr = *(const float4*)(r + base + t * 4);
    float4 s  = make_float4(xa.x + xr.x, xa.y + xr.y, xa.z + xr.z, xa.w + xr.w);
    float sum = s.x + s.y + s.z + s.w;
    float sq  = s.x * s.x + s.y * s.y + s.z * s.z + s.w * s.w;
#pragma unroll
    for (int o = 16; o; o >>= 1) {
        sum += __shfl_xor_sync(0xffffffffu, sum, o);
        sq  += __shfl_xor_sync(0xffffffffu, sq,  o);
    }
    __shared__ float ssum[8], ssq[8];
    __shared__ float s_mu, s_inv;
    int w = t >> 5;
    if ((t & 31) == 0) { ssum[w] = sum; ssq[w] = sq; }
    __syncthreads();
    if (t == 0) {
        float ts = 0.f, tq = 0.f;
        for (int i = 0; i < 8; i++) { ts += ssum[i]; tq += ssq[i]; }
        float mu  = ts * (1.f / 1024.f);
        float var = tq * (1.f / 1024.f) - mu * mu;
        s_mu = mu;
        s_inv = rsqrtf(var + 1e-6f);
    }
    __syncthreads();
    float mu = s_mu, inv = s_inv;
    float4 gg = *(const float4*)(g + t * 4);
    float4 bb = *(const float4*)(b + t * 4);
    float4 o = make_float4((s.x - mu) * inv * gg.x + bb.x,
                           (s.y - mu) * inv * gg.y + bb.y,
                           (s.z - mu) * inv * gg.z + bb.z,
                           (s.w - mu) * inv * gg.w + bb.w);
    *(float4*)(out + base + t * 4) = o;
}

// ---------------- driver -----------------------------------------------------
extern "C" void kernel_launch(void* const* d_in, const int* in_sizes, int n_in,
                              void* d_out, int out_size)
{
    const float* x    = (const float*)d_in[0];
    const float* wq   = (const float*)d_in[1];
    const float* wk   = (const float*)d_in[2];
    const float* wv   = (const float*)d_in[3];
    const float* wo   = (const float*)d_in[4];
    const float* proj = (const float*)d_in[5];
    const float* ln1g = (const float*)d_in[6];
    const float* ln1b = (const float*)d_in[7];
    const float* ln2g = (const float*)d_in[8];
    const float* ln2b = (const float*)d_in[9];
    const float* w1   = (const float*)d_in[10];
    const float* b1   = (const float*)d_in[11];
    const float* w2   = (const float*)d_in[12];
    const float* b2   = (const float*)d_in[13];
    float* out = (float*)d_out;

    float *p_q, *p_k, *p_v, *p_qp, *p_kp, *p_kv, *p_ksum, *p_den;
    float *p_attn, *p_tmp, *p_out1, *p_h, *p_pT;
    unsigned* p_kmax;
    cudaGetSymbolAddress((void**)&p_q,    g_q);
    cudaGetSymbolAddress((void**)&p_k,    g_k);
    cudaGetSymbolAddress((void**)&p_v,    g_v);
    cudaGetSymbolAddress((void**)&p_qp,   g_qp);
    cudaGetSymbolAddress((void**)&p_kp,   g_kp);
    cudaGetSymbolAddress((void**)&p_kv,   g_kv);
    cudaGetSymbolAddress((void**)&p_ksum, g_ksum);
    cudaGetSymbolAddress((void**)&p_den,  g_den);
    cudaGetSymbolAddress((void**)&p_attn, g_attn);
    cudaGetSymbolAddress((void**)&p_tmp,  g_tmp);
    cudaGetSymbolAddress((void**)&p_out1, g_out1);
    cudaGetSymbolAddress((void**)&p_h,    g_hbuf);
    cudaGetSymbolAddress((void**)&p_pT,   g_projT);
    cudaGetSymbolAddress((void**)&p_kmax, g_kmax);

    // projT = dn * proj^T
    k_projT<<<64, 256>>>(proj, p_pT);

    // q,k,v projections: [16384,1024] = x @ w  (w flattens to [1024,1024])
    tgemm<EPI_NONE><<<dim3(8, 128), 256>>>(x, wq, nullptr, p_q, NT, 1024, 1024);
    tgemm<EPI_NONE><<<dim3(8, 128), 256>>>(x, wk, nullptr, p_k, NT, 1024, 1024);
    tgemm<EPI_NONE><<<dim3(8, 128), 256>>>(x, wv, nullptr, p_v, NT, 1024, 1024);

    // dd = q_resh[262144,64] @ projT[64,256]  (same for k)
    tgemm<EPI_NONE><<<dim3(2, 2048), 256>>>(p_q, p_pT, nullptr, p_qp, NR, 256, 64);
    tgemm<EPI_NONE><<<dim3(2, 2048), 256>>>(p_k, p_pT, nullptr, p_kp, NR, 256, 64);

    cudaMemsetAsync(p_kmax, 0, 4);
    cudaMemsetAsync(p_ksum, 0, BB * HH * MMF * sizeof(float));

    // global max over key dd
    k_max<<<2048, 256>>>((const float4*)p_kp, (size_t)NR * 64, p_kmax);

    // feature maps in place
    k_expq<<<NR / 8, 256>>>(p_qp, p_q);
    k_expk<<<NR / 8, 256>>>(p_kp, p_k, p_kmax);

    // kv[bh][256][64] = kp^T @ v per (b,h):  M=256 N=64 K=4096
    sgemm_bh<true, false><<<dim3(1, 2, 64), 256>>>(
        p_kp, (size_t)16777216, (size_t)256, 4096,
        p_v,  (size_t)4194304,  (size_t)64,  1024,
        p_kv, (size_t)(16 * 16384), (size_t)16384, 64,
        nullptr, 0, 0, 0,
        256, 64, 4096);

    // ksum
    k_ksum<<<dim3(8, 64), 256>>>(p_kp, p_ksum);

    // denom per (t,h)
    k_denom<<<NR / 8, 256>>>(p_qp, p_ksum, p_den);

    // attn = (qp @ kv) / denom per (b,h): M=4096 N=64 K=256
    sgemm_bh<false, true><<<dim3(1, 32, 64), 256>>>(
        p_qp, (size_t)16777216, (size_t)256, 4096,
        p_kv, (size_t)(16 * 16384), (size_t)16384, 64,
        p_attn, (size_t)4194304, (size_t)64, 1024,
        p_den,  (size_t)65536,   (size_t)1,  16,
        4096, 64, 256);

    // attn_out = attn @ wo  (wo flattens to [1024,1024], rows = h*64+k)
    tgemm<EPI_NONE><<<dim3(8, 128), 256>>>(p_attn, wo, nullptr, p_tmp, NT, 1024, 1024);

    // out1 = LN(x + attn_out)
    k_ln<<<NT, 256>>>(p_tmp, x, ln1g, ln1b, p_out1);

    // FFN
    tgemm<EPI_BIAS_ELU><<<dim3(32, 128), 256>>>(p_out1, w1, b1, p_h, NT, DFF, 1024);
    tgemm<EPI_BIAS><<<dim3(8, 128), 256>>>(p_h, w2, b2, p_tmp, NT, 1024, DFF);

    // out2 = LN(out1 + ffn)
    k_ln<<<NT, 256>>>(p_tmp, p_out1, ln2g, ln2b, out);
}